// round 12
// baseline (speedup 1.0000x reference)
#include <cuda_runtime.h>

// OrbitalAEVComputer: coefficients [64,256,45] f32 -> out [64,256,4608] f32
// Per (conf,atom): 12 AOVs (4 p + 8 reordered d), radial 12*32, angular 66*8*8.
// 2 atoms per 256-thread block: half = t>>7 picks the atom, tl = t&127 is the
// R10-proven per-atom schedule. Fewer blocks + more resident warps per SM.

#define NATOMS_TOTAL (64 * 256)
#define NBLOCKS (NATOMS_TOTAL / 2)
#define OUT_STRIDE 4608
#define NPAIR 66

// cos/sin of shfZ = linspace(0.19634954, 2.94524311, 8)  (odd multiples of pi/16)
__constant__ float COSZ[8] = {
     0.98078528f,  0.83146961f,  0.55557023f,  0.19509032f,
    -0.19509032f, -0.55557023f, -0.83146961f, -0.98078528f
};
__constant__ float SINZ[8] = {
     0.19509032f,  0.55557023f,  0.83146961f,  0.98078528f,
     0.98078528f,  0.83146961f,  0.55557023f,  0.19509032f
};

// triu_indices(12, k=1), i-major
__constant__ unsigned char IU[NPAIR] = {
    0,0,0,0,0,0,0,0,0,0,0,
    1,1,1,1,1,1,1,1,1,1,
    2,2,2,2,2,2,2,2,2,
    3,3,3,3,3,3,3,3,
    4,4,4,4,4,4,4,
    5,5,5,5,5,5,
    6,6,6,6,6,
    7,7,7,7,
    8,8,8,
    9,9,
    10
};
__constant__ unsigned char JU[NPAIR] = {
    1,2,3,4,5,6,7,8,9,10,11,
    2,3,4,5,6,7,8,9,10,11,
    3,4,5,6,7,8,9,10,11,
    4,5,6,7,8,9,10,11,
    5,6,7,8,9,10,11,
    6,7,8,9,10,11,
    7,8,9,10,11,
    8,9,10,11,
    9,10,11,
    10,11,
    11
};

// 256-bit store (sm_100+): one instruction writes a full 32B row; lanes at 32B
// stride -> 1024B dense per warp = 8 wavefronts (the minimum).
__device__ __forceinline__ void stg256(float* p,
                                       float v0, float v1, float v2, float v3,
                                       float v4, float v5, float v6, float v7)
{
    asm volatile("st.global.v8.f32 [%0], {%1,%2,%3,%4,%5,%6,%7,%8};"
                 :: "l"(p), "f"(v0), "f"(v1), "f"(v2), "f"(v3),
                           "f"(v4), "f"(v5), "f"(v6), "f"(v7)
                 : "memory");
}

__global__ __launch_bounds__(256, 5)
void orbital_aev_kernel(const float* __restrict__ coeff, float* __restrict__ out)
{
    __shared__ float  dsh[2][12];
    __shared__ float  nvsh[2][12][3];
    __shared__ float4 pairsh[2][NPAIR];  // (cz = 0.95*cos, sz = sqrt(1-cz^2), avdist, 0)

    const int t    = threadIdx.x;
    const int half = t >> 7;             // which atom of the pair
    const int tl   = t & 127;            // per-atom thread id (R10 schedule)
    const size_t atom = (size_t)blockIdx.x * 2 + half;
    const float* __restrict__ c = coeff + atom * 45;
    float* __restrict__ o = out + atom * OUT_STRIDE;

    // ---- Build 12 AOVs: dist + normalized vectors into SMEM ----
    if (tl < 12) {
        float x, y, z;
        if (tl < 4) {
            int b = 9 + 3 * tl;
            x = c[b]; y = c[b + 1]; z = c[b + 2];
        } else {
            int r = (tl - 4) >> 1;
            int b = 21 + 6 * r;
            if (((tl - 4) & 1) == 0) {       // d row picks [0,2,5]
                x = c[b];     y = c[b + 2]; z = c[b + 5];
            } else {                          // then [4,3,1]
                x = c[b + 4]; y = c[b + 3]; z = c[b + 1];
            }
        }
        float s = x * x + y * y + z * z;
        float inv, d;
        if (s > 1e-24f) { inv = rsqrtf(s); d = s * inv; }
        else            { inv = 0.0f;      d = 0.0f;    }
        dsh[half][tl] = d;
        nvsh[half][tl][0] = x * inv;
        nvsh[half][tl][1] = y * inv;
        nvsh[half][tl][2] = z * inv;
    }
    __syncthreads();

    // ---- Middle phase: DISJOINT thread ranges run concurrently. ----
    // tl in [0,66): pair terms cz/sz/avdist into SMEM.
    // tl in [66,114): radial outputs (s_aev == r_aev; 48 x STG.256).
    if (tl < NPAIR) {
        int i = IU[tl], j = JU[tl];
        float cc = nvsh[half][i][0] * nvsh[half][j][0]
                 + nvsh[half][i][1] * nvsh[half][j][1]
                 + nvsh[half][i][2] * nvsh[half][j][2];
        float cz = 0.95f * cc;
        float sz = sqrtf(fmaxf(0.0f, 1.0f - cz * cz));
        float av = 0.5f * (dsh[half][i] + dsh[half][j]);
        pairsh[half][tl] = make_float4(cz, sz, av, 0.0f);
    } else if (tl < NPAIR + 48) {
        int r   = tl - NPAIR;
        int aov = r >> 2;
        int q   = r & 3;
        float d  = dsh[half][aov];
        int   kb = (q & 1) << 3;
        float v[8];
        #pragma unroll
        for (int j = 0; j < 8; j++) {
            float u = d - (0.5f + 0.2f * (float)(kb + j));
            v[j] = __expf(-16.0f * u * u);
        }
        stg256(o + (aov << 5) + (q << 3),
               v[0], v[1], v[2], v[3], v[4], v[5], v[6], v[7]);
    }
    __syncthreads();

    // ---- Angular: 528 row-tasks per atom (pair p, z = m&7 = tl&7 invariant).
    //      One pow32 + 8 exps + one STG.256 per task. ----
    const float cosz = COSZ[tl & 7];
    const float sinz = SINZ[tl & 7];
    #pragma unroll
    for (int iter = 0; iter < 5; iter++) {
        int m = tl + 128 * iter;
        if (m < 528) {
            int p = m >> 3;
            float4 cs = pairsh[half][p];              // 8-way broadcast LDS.128

            // factor1: cos(angle - shfZ) = cz*cosZ + sqrt(1-cz^2)*sinZ (exact identity)
            float cosd = fmaf(cs.x, cosz, cs.y * sinz);
            float b = fmaf(0.5f, cosd, 0.5f);         // (1+cosd)/2 in [0,1]
            float q2 = b * b;                         // ^2
            q2 *= q2;                                 // ^4
            q2 *= q2;                                 // ^8
            q2 *= q2;                                 // ^16
            q2 *= q2;                                 // ^32
            float g = 2.0f * q2;

            // factor2 for all 8 shfA = 0.5 + (3/7)*a
            float av = cs.z;
            float f2v[8];
            #pragma unroll
            for (int a = 0; a < 8; a++) {
                float ua = av - (0.5f + (3.0f / 7.0f) * (float)a);
                f2v[a] = __expf(-8.0f * ua * ua);
            }

            stg256(o + 384 + (m << 3),
                   g * f2v[0], g * f2v[1], g * f2v[2], g * f2v[3],
                   g * f2v[4], g * f2v[5], g * f2v[6], g * f2v[7]);
        }
    }
}

extern "C" void kernel_launch(void* const* d_in, const int* in_sizes, int n_in,
                              void* d_out, int out_size)
{
    const float* coeff = (const float*)d_in[0];
    float* out = (float*)d_out;
    orbital_aev_kernel<<<NBLOCKS, 256>>>(coeff, out);
}